// round 8
// baseline (speedup 1.0000x reference)
#include <cuda_runtime.h>
#include <cstddef>

#define NNODE 10000
#define NEDGE 160000

// ---------------- scratch (static device globals; no allocation) ----------------
__device__ float g_h[NEDGE * 64];            // fc hidden (after layer 2)
__device__ float g_w[NEDGE * 512];           // edge weights w = h @ fc_w2 / 8
__device__ float g_ys[NNODE * 128];          // y_s
__device__ float g_yvt[3 * NNODE * 128];     // y_v, [c][n][u]
__device__ float g_scs[NNODE * 128];         // sc_s
__device__ float g_scvt[3 * NNODE * 128];    // sc_v, [c][n][w]
__device__ float g_aggs[NNODE * 256];        // aggregated s (pre lin2, pre inv)
__device__ float g_aggvt[3 * NNODE * 256];   // aggregated v, [c][n][p]
__device__ float g_outs[NNODE * 128];
__device__ float g_outvt[3 * NNODE * 128];
__device__ int   g_cnt[NNODE];
__device__ int   g_pos[NNODE];
__device__ int   g_rowstart[NNODE + 1];
__device__ int   g_eid[NEDGE];

// ---------------- packed fp32x2 helpers (Blackwell FFMA2 path) ------------------
__device__ __forceinline__ unsigned long long pack2(float lo, float hi)
{
    unsigned long long r;
    asm("mov.b64 %0, {%1, %2};" : "=l"(r)
        : "r"(__float_as_uint(lo)), "r"(__float_as_uint(hi)));
    return r;
}
__device__ __forceinline__ void fma2(unsigned long long& d,
                                     unsigned long long a, unsigned long long b)
{
    asm("fma.rn.f32x2 %0, %1, %2, %0;" : "+l"(d) : "l"(a), "l"(b));
}
__device__ __forceinline__ float2 unpack2(unsigned long long v)
{
    unsigned int lo, hi;
    asm("mov.b64 {%0, %1}, %2;" : "=r"(lo), "=r"(hi) : "l"(v));
    return make_float2(__uint_as_float(lo), __uint_as_float(hi));
}

// ---------------- generic tiled SGEMM, C = alpha * A@B (+ D) -------------------
// BM=BN=128, BK=8, 256 threads, 8x8 microtile via packed f32x2 FMAs.
// Row-major A (M x K), B (K x Ncols, ldb = Ncols), C/D (M x Ncols).
// K % 8 == 0, Ncols % 128 == 0, M guarded.
// AMODE 0: A[m*lda + k]
// AMODE 1: Z_s: node_feats[m*512 + k/10] * attrs[m*10 + k%10]
// AMODE 2: Z_v: rows m=(c*NNODE+n): node_feats[n*512+128+(k/10)*3+c]*attrs[n*10+k%10]
// AMODE 3: x_v: rows m=(c*NNODE+n): node_feats[n*512+128+k*3+c]
template <int AMODE>
__global__ void __launch_bounds__(256) k_sgemm(
    const float* __restrict__ A, const float* __restrict__ B,
    float* __restrict__ C, const float* __restrict__ D,
    const float* __restrict__ attrs,
    int M, int K, int Ncols, int lda, float alpha)
{
    __shared__ __align__(16) float As[8][128];
    __shared__ __align__(16) unsigned long long Bs2[8][128];  // {b,b} duplicated
    const int tid = threadIdx.x;
    const int bm = blockIdx.y * 128;
    const int bn = blockIdx.x * 128;
    const int tx = tid & 15;
    const int ty = tid >> 4;
    const int row0 = ty * 8;
    const int col0 = tx * 8;

    const int kA  = tid & 7;
    const int mA0 = tid >> 3;      // + 32*s
    const int nB  = tid & 127;
    const int kB0 = tid >> 7;      // + 2*s

    int mg[4], an[4], ac[4];
#pragma unroll
    for (int s = 0; s < 4; ++s) {
        int m = bm + mA0 + 32 * s;
        mg[s] = m;
        int c = m / NNODE;
        an[s] = m - c * NNODE;
        ac[s] = c;
    }

    unsigned long long acc[4][8];  // rows (row0+2*i2, row0+2*i2+1) x cols (col0+j)
#pragma unroll
    for (int i = 0; i < 4; ++i)
#pragma unroll
        for (int j = 0; j < 8; ++j) acc[i][j] = 0ull;

    for (int k0 = 0; k0 < K; k0 += 8) {
#pragma unroll
        for (int s = 0; s < 4; ++s) {
            int m = mg[s];
            int kk = k0 + kA;
            float v = 0.f;
            if (m < M) {
                if (AMODE == 0) {
                    v = __ldg(A + (size_t)m * lda + kk);
                } else if (AMODE == 1) {
                    int u = kk / 10, vv = kk - u * 10;
                    v = __ldg(A + (size_t)m * 512 + u) * __ldg(attrs + m * 10 + vv);
                } else if (AMODE == 2) {
                    int u = kk / 10, vv = kk - u * 10;
                    v = __ldg(A + (size_t)an[s] * 512 + 128 + u * 3 + ac[s]) *
                        __ldg(attrs + an[s] * 10 + vv);
                } else {
                    v = __ldg(A + (size_t)an[s] * 512 + 128 + kk * 3 + ac[s]);
                }
            }
            As[kA][mA0 + 32 * s] = v;
        }
#pragma unroll
        for (int s = 0; s < 4; ++s) {
            int kk = kB0 + 2 * s;
            float v = __ldg(B + (size_t)(k0 + kk) * Ncols + bn + nB);
            Bs2[kk][nB] = pack2(v, v);
        }
        __syncthreads();
#pragma unroll
        for (int k = 0; k < 8; ++k) {
            ulonglong2 a01 = *(const ulonglong2*)&As[k][row0];
            ulonglong2 a23 = *(const ulonglong2*)&As[k][row0 + 4];
            unsigned long long Au[4] = {a01.x, a01.y, a23.x, a23.y};
            const ulonglong2* bp = (const ulonglong2*)&Bs2[k][col0];
            ulonglong2 b01 = bp[0], b23 = bp[1], b45 = bp[2], b67 = bp[3];
            unsigned long long Bu[8] = {b01.x, b01.y, b23.x, b23.y,
                                        b45.x, b45.y, b67.x, b67.y};
#pragma unroll
            for (int i2 = 0; i2 < 4; ++i2)
#pragma unroll
                for (int j = 0; j < 8; ++j)
                    fma2(acc[i2][j], Au[i2], Bu[j]);
        }
        __syncthreads();
    }

#pragma unroll
    for (int i2 = 0; i2 < 4; ++i2) {
        float lo[8], hi[8];
#pragma unroll
        for (int j = 0; j < 8; ++j) {
            float2 v = unpack2(acc[i2][j]);
            lo[j] = v.x; hi[j] = v.y;
        }
#pragma unroll
        for (int h = 0; h < 2; ++h) {
            int m = bm + row0 + 2 * i2 + h;
            if (m >= M) continue;
            size_t off = (size_t)m * Ncols + bn + col0;
            float r[8];
#pragma unroll
            for (int j = 0; j < 8; ++j) r[j] = alpha * (h ? hi[j] : lo[j]);
            if (D) {
                float4 d0 = __ldg((const float4*)(D + off));
                float4 d1 = __ldg((const float4*)(D + off + 4));
                r[0] += d0.x; r[1] += d0.y; r[2] += d0.z; r[3] += d0.w;
                r[4] += d1.x; r[5] += d1.y; r[6] += d1.z; r[7] += d1.w;
            }
            *(float4*)(C + off)     = make_float4(r[0], r[1], r[2], r[3]);
            *(float4*)(C + off + 4) = make_float4(r[4], r[5], r[6], r[7]);
        }
    }
}

// ---------------- fc layers 0+1 (8->64->64 with scaled SiLU) --------------------
__device__ __forceinline__ float siluc(float x)
{
    return 1.679f * x * (1.0f / (1.0f + __expf(-x)));
}

// 256 threads: 32 edges per round, 8 threads per edge, 8 outputs per thread.
// f32x2 math, 16B shared weight loads. NEDGE % (1250*32) == 0 -> no guards.
__global__ void __launch_bounds__(256) k_fc01(
    const float* __restrict__ ef, const float* __restrict__ w0,
    const float* __restrict__ w1)
{
    __shared__ __align__(16) float w0s[8 * 64];
    __shared__ __align__(16) float w1s[64 * 64];
    __shared__ float h0s[32][68];  // pad 68: 4 edge-groups hit distinct banks
    const int tid = threadIdx.x;
    const float rs8 = 0.35355339059327373f;  // 1/sqrt(8)
    for (int i = tid; i < 8 * 64; i += 256)  w0s[i] = w0[i] * rs8;
    for (int i = tid; i < 64 * 64; i += 256) w1s[i] = w1[i] * 0.125f;
    __syncthreads();
    const int e8 = tid >> 3;          // 0..31: edge within round
    const int j8 = (tid & 7) * 8;     // output group

    for (int base = blockIdx.x * 32; base < NEDGE; base += gridDim.x * 32) {
        int e = base + e8;
        float4 ef0 = __ldg((const float4*)(ef + (size_t)e * 8));
        float4 ef1 = __ldg((const float4*)(ef + (size_t)e * 8 + 4));
        float efr[8] = {ef0.x, ef0.y, ef0.z, ef0.w, ef1.x, ef1.y, ef1.z, ef1.w};

        // layer 0: 8 -> 64
        unsigned long long a0[4] = {0ull, 0ull, 0ull, 0ull};
#pragma unroll
        for (int k = 0; k < 8; ++k) {
            unsigned long long av = pack2(efr[k], efr[k]);
            ulonglong2 wA = *(const ulonglong2*)&w0s[k * 64 + j8];
            ulonglong2 wB = *(const ulonglong2*)&w0s[k * 64 + j8 + 4];
            fma2(a0[0], av, wA.x);
            fma2(a0[1], av, wA.y);
            fma2(a0[2], av, wB.x);
            fma2(a0[3], av, wB.y);
        }
#pragma unroll
        for (int t = 0; t < 4; ++t) {
            float2 v = unpack2(a0[t]);
            h0s[e8][j8 + 2 * t]     = siluc(v.x);
            h0s[e8][j8 + 2 * t + 1] = siluc(v.y);
        }
        __syncthreads();

        // layer 1: 64 -> 64
        unsigned long long a1[4] = {0ull, 0ull, 0ull, 0ull};
#pragma unroll 8
        for (int k = 0; k < 64; ++k) {
            float h = h0s[e8][k];
            unsigned long long av = pack2(h, h);
            ulonglong2 wA = *(const ulonglong2*)&w1s[k * 64 + j8];
            ulonglong2 wB = *(const ulonglong2*)&w1s[k * 64 + j8 + 4];
            fma2(a1[0], av, wA.x);
            fma2(a1[1], av, wA.y);
            fma2(a1[2], av, wB.x);
            fma2(a1[3], av, wB.y);
        }
        float o[8];
#pragma unroll
        for (int t = 0; t < 4; ++t) {
            float2 v = unpack2(a1[t]);
            o[2 * t]     = siluc(v.x);
            o[2 * t + 1] = siluc(v.y);
        }
        float* dst = g_h + (size_t)e * 64 + j8;
        *(float4*)(dst)     = make_float4(o[0], o[1], o[2], o[3]);
        *(float4*)(dst + 4) = make_float4(o[4], o[5], o[6], o[7]);
        __syncthreads();
    }
}

// ---------------- CSR build ----------------------------------------------------
__global__ void k_count(const int* __restrict__ ei)
{
    int e = blockIdx.x * 256 + threadIdx.x;
    if (e < NEDGE) atomicAdd(&g_cnt[ei[e]], 1);
}

__global__ void k_scan()
{
    __shared__ int sm[256];
    const int tid = threadIdx.x;
    const int CH = (NNODE + 255) / 256;
    int beg = tid * CH;
    int end = min(beg + CH, NNODE);
    int s = 0;
    for (int i = beg; i < end; ++i) s += g_cnt[i];
    sm[tid] = s;
    __syncthreads();
    for (int off = 1; off < 256; off <<= 1) {
        int v = 0;
        if (tid >= off) v = sm[tid - off];
        __syncthreads();
        sm[tid] += v;
        __syncthreads();
    }
    int run = sm[tid] - s;
    for (int i = beg; i < end; ++i) {
        g_rowstart[i] = run;
        g_pos[i] = run;
        run += g_cnt[i];
    }
    if (tid == 255) g_rowstart[NNODE] = sm[255];
}

__global__ void k_fill(const int* __restrict__ ei)
{
    int e = blockIdx.x * 256 + threadIdx.x;
    if (e < NEDGE) {
        int d = ei[e];
        int p = atomicAdd(&g_pos[d], 1);
        g_eid[p] = e;
    }
}

// ---------------- message + aggregation: one warp per node, no float atomics ---
__global__ void __launch_bounds__(256) k_agg(const int* __restrict__ ei,
                                             const float* __restrict__ eattr)
{
    int gw = (blockIdx.x * blockDim.x + threadIdx.x) >> 5;
    int lane = threadIdx.x & 31;
    if (gw >= NNODE) return;
    const int n = gw;
    const int u0 = lane * 4;
    const float inv_sq3 = 0.5773502691896258f;

    float s0[4] = {0, 0, 0, 0}, s1[4] = {0, 0, 0, 0};
    float v2[3][4] = {{0}}, v3[3][4] = {{0}};

    const int beg = g_rowstart[n];
    const int end = g_rowstart[n + 1];
    for (int i = beg; i < end; ++i) {
        int e = g_eid[i];
        float4 ea = __ldg((const float4*)(eattr + (size_t)e * 4));
        int s = ei[NEDGE + e];  // src = edge_index[1]
        const float* wr = g_w + (size_t)e * 512 + u0;
        float4 wss = __ldg((const float4*)(wr));
        float4 wsv = __ldg((const float4*)(wr + 128));
        float4 wvs = __ldg((const float4*)(wr + 256));
        float4 wvv = __ldg((const float4*)(wr + 384));
        const float* yb = g_ys + (size_t)s * 128 + u0;
        float4 xs = __ldg((const float4*)(yb));
        const float* vb = g_yvt + (size_t)s * 128 + u0;
        float4 x0 = __ldg((const float4*)(vb));
        float4 x1 = __ldg((const float4*)(vb + NNODE * 128));
        float4 x2 = __ldg((const float4*)(vb + 2 * NNODE * 128));

        float as_ = ea.x, av0 = ea.y, av1 = ea.z, av2 = ea.w;
        float WSS[4] = {wss.x, wss.y, wss.z, wss.w};
        float WSV[4] = {wsv.x, wsv.y, wsv.z, wsv.w};
        float WVS[4] = {wvs.x, wvs.y, wvs.z, wvs.w};
        float WVV[4] = {wvv.x, wvv.y, wvv.z, wvv.w};
        float XS[4]  = {xs.x, xs.y, xs.z, xs.w};
        float X0[4]  = {x0.x, x0.y, x0.z, x0.w};
        float X1[4]  = {x1.x, x1.y, x1.z, x1.w};
        float X2[4]  = {x2.x, x2.y, x2.z, x2.w};
#pragma unroll
        for (int t = 0; t < 4; ++t) {
            s0[t] = fmaf(WSS[t] * as_, XS[t], s0[t]);
            float dot = X0[t] * av0 + X1[t] * av1 + X2[t] * av2;
            s1[t] = fmaf(WVV[t] * inv_sq3, dot, s1[t]);
            float tsv = WSV[t] * XS[t];
            v2[0][t] = fmaf(tsv, av0, v2[0][t]);
            v2[1][t] = fmaf(tsv, av1, v2[1][t]);
            v2[2][t] = fmaf(tsv, av2, v2[2][t]);
            float tvs = WVS[t] * as_;
            v3[0][t] = fmaf(tvs, X0[t], v3[0][t]);
            v3[1][t] = fmaf(tvs, X1[t], v3[1][t]);
            v3[2][t] = fmaf(tvs, X2[t], v3[2][t]);
        }
    }

    float* sp = g_aggs + (size_t)n * 256 + u0;
    *(float4*)(sp)       = make_float4(s0[0], s0[1], s0[2], s0[3]);
    *(float4*)(sp + 128) = make_float4(s1[0], s1[1], s1[2], s1[3]);
#pragma unroll
    for (int c = 0; c < 3; ++c) {
        float* vp = g_aggvt + (size_t)c * NNODE * 256 + (size_t)n * 256 + u0;
        *(float4*)(vp)       = make_float4(v2[c][0], v2[c][1], v2[c][2], v2[c][3]);
        *(float4*)(vp + 128) = make_float4(v3[c][0], v3[c][1], v3[c][2], v3[c][3]);
    }
}

// ---------------- final packing ------------------------------------------------
__global__ void k_pack(float* __restrict__ out)
{
    int idx = blockIdx.x * 256 + threadIdx.x;  // NNODE*128 threads exactly
    int n = idx >> 7, wcol = idx & 127;
    float* o = out + (size_t)n * 512;
    o[wcol] = g_outs[idx];
    o[128 + wcol * 3 + 0] = g_outvt[idx];
    o[128 + wcol * 3 + 1] = g_outvt[NNODE * 128 + idx];
    o[128 + wcol * 3 + 2] = g_outvt[2 * NNODE * 128 + idx];
}

// ---------------- launch -------------------------------------------------------
extern "C" void kernel_launch(void* const* d_in, const int* in_sizes, int n_in,
                              void* d_out, int out_size)
{
    const float* node_feats = (const float*)d_in[0];
    const float* node_attrs = (const float*)d_in[1];
    const float* edge_feats = (const float*)d_in[2];
    const float* edge_attrs = (const float*)d_in[3];
    const int*   edge_index = (const int*)d_in[4];
    const float* lin1_ws = (const float*)d_in[5];
    const float* lin1_wv = (const float*)d_in[6];
    const float* fc_w0   = (const float*)d_in[7];
    const float* fc_w1   = (const float*)d_in[8];
    const float* fc_w2   = (const float*)d_in[9];
    const float* lin2_ws = (const float*)d_in[10];
    const float* lin2_wv = (const float*)d_in[11];
    const float* sc_ws   = (const float*)d_in[12];
    const float* sc_wv   = (const float*)d_in[13];
    float* out = (float*)d_out;

    float *p_h, *p_w, *p_ys, *p_yvt, *p_scs, *p_scvt, *p_aggs, *p_aggvt, *p_outs, *p_outvt;
    int* p_cnt;
    cudaGetSymbolAddress((void**)&p_h, g_h);
    cudaGetSymbolAddress((void**)&p_w, g_w);
    cudaGetSymbolAddress((void**)&p_ys, g_ys);
    cudaGetSymbolAddress((void**)&p_yvt, g_yvt);
    cudaGetSymbolAddress((void**)&p_scs, g_scs);
    cudaGetSymbolAddress((void**)&p_scvt, g_scvt);
    cudaGetSymbolAddress((void**)&p_aggs, g_aggs);
    cudaGetSymbolAddress((void**)&p_aggvt, g_aggvt);
    cudaGetSymbolAddress((void**)&p_outs, g_outs);
    cudaGetSymbolAddress((void**)&p_outvt, g_outvt);
    cudaGetSymbolAddress((void**)&p_cnt, g_cnt);

    const float L1S  = 0.08838834764831845f;   // 1/sqrt(128)
    const float SCN  = 0.027950849718747373f;  // 1/sqrt(1280)
    const float OUTA = 0.015625f;              // (1/sqrt(16)) * (1/sqrt(256))

    // CSR build
    cudaMemsetAsync(p_cnt, 0, NNODE * sizeof(int));
    k_count<<<625, 256>>>(edge_index);
    k_scan<<<1, 256>>>();
    k_fill<<<625, 256>>>(edge_index);

    // fc small layers -> g_h
    k_fc01<<<1250, 256>>>(edge_feats, fc_w0, fc_w1);
    // edge weights: w = h @ fc_w2 / 8   (E x 64) @ (64 x 512)
    k_sgemm<0><<<dim3(4, 1250), 256>>>(p_h, fc_w2, p_w, nullptr, nullptr,
                                       NEDGE, 64, 512, 64, 0.125f);

    // node linear transforms
    k_sgemm<0><<<dim3(1, 79), 256>>>(node_feats, lin1_ws, p_ys, nullptr, nullptr,
                                     NNODE, 128, 128, 512, L1S);
    k_sgemm<3><<<dim3(1, 235), 256>>>(node_feats, lin1_wv, p_yvt, nullptr, nullptr,
                                      3 * NNODE, 128, 128, 0, L1S);
    // self-connection einsums
    k_sgemm<1><<<dim3(1, 79), 256>>>(node_feats, sc_ws, p_scs, nullptr, node_attrs,
                                     NNODE, 1280, 128, 0, SCN);
    k_sgemm<2><<<dim3(1, 235), 256>>>(node_feats, sc_wv, p_scvt, nullptr, node_attrs,
                                      3 * NNODE, 1280, 128, 0, SCN);

    // messages + segment sum (CSR, warp per node, register accumulators)
    k_agg<<<1250, 256>>>(edge_index, edge_attrs);

    // output linear + skip connection
    k_sgemm<0><<<dim3(1, 79), 256>>>(p_aggs, lin2_ws, p_outs, p_scs, nullptr,
                                     NNODE, 256, 128, 256, OUTA);
    k_sgemm<0><<<dim3(1, 235), 256>>>(p_aggvt, lin2_wv, p_outvt, p_scvt, nullptr,
                                      3 * NNODE, 256, 128, 256, OUTA);

    // pack to output layout [out_s | out_v (w-major, c-minor)]
    k_pack<<<5000, 256>>>(out);
}

// round 11
// speedup vs baseline: 2.6971x; 2.6971x over previous
#include <cuda_runtime.h>
#include <cstddef>

#define NNODE 10000
#define NEDGE 160000

// ---------------- scratch (static device globals; no allocation) ----------------
__device__ float g_h[NEDGE * 64];            // fc hidden (after layer 2)
__device__ float g_w[NEDGE * 512];           // edge weights w = h @ fc_w2 / 8
__device__ float g_ys[NNODE * 128];          // y_s
__device__ float g_yvt[3 * NNODE * 128];     // y_v, [c][n][u]
__device__ float g_scs[NNODE * 128];         // sc_s
__device__ float g_scvt[3 * NNODE * 128];    // sc_v, [c][n][w]
__device__ float g_aggs[NNODE * 256];        // aggregated s (pre lin2)
__device__ float g_aggvt[3 * NNODE * 256];   // aggregated v, [c][n][p]
__device__ int   g_cnt[NNODE];
__device__ int   g_pos[NNODE];
__device__ int   g_rowstart[NNODE + 1];
__device__ int   g_eid[NEDGE];

#define L1S_C  0.08838834764831845f    // 1/sqrt(128)
#define SCN_C  0.027950849718747373f   // 1/sqrt(1280)
#define OUTA_C 0.015625f               // (1/sqrt(16)) * (1/sqrt(256))

// ---------------- SGEMM body, C = alpha * A@B (+ D) ----------------------------
// BM=BN=128, BK=8, 256 threads, 8x8 microtile, plain FFMA (round-7 proven path).
// AMODE 0: A[m*lda + k]
// AMODE 1: Z_s: node_feats[m*512 + k/10] * attrs[m*10 + k%10]
// AMODE 2: Z_v: rows m=(c*NNODE+n): node_feats[n*512+128+(k/10)*3+c]*attrs[n*10+k%10]
// AMODE 3: x_v: rows m=(c*NNODE+n): node_feats[n*512+128+k*3+c]
// OMODE 0: C[m*Ncols + col]             (plain)
// OMODE 1: C[m*512 + col]               (packed out, scalar part)
// OMODE 2: C[n*512 + 128 + col*3 + c]   (packed out, vector part; m=c*NNODE+n)
template <int AMODE, int OMODE>
__device__ __forceinline__ void sgemm_body(
    float (*As)[128], float (*Bs)[128],
    int bx, int by,
    const float* __restrict__ A, const float* __restrict__ B,
    float* __restrict__ C, const float* __restrict__ D,
    const float* __restrict__ attrs,
    int M, int K, int Ncols, int lda, float alpha)
{
    const int tid = threadIdx.x;
    const int bm = by * 128;
    const int bn = bx * 128;
    const int tx = tid & 15;
    const int ty = tid >> 4;
    const int row0 = ty * 8;
    const int col0 = tx * 8;

    const int kA  = tid & 7;
    const int mA0 = tid >> 3;      // + 32*s
    const int nB  = tid & 127;
    const int kB0 = tid >> 7;      // + 2*s

    int mg[4], an[4], ac[4];
#pragma unroll
    for (int s = 0; s < 4; ++s) {
        int m = bm + mA0 + 32 * s;
        mg[s] = m;
        if (AMODE >= 2) {
            int c = m / NNODE;
            an[s] = m - c * NNODE;
            ac[s] = c;
        } else {
            an[s] = m; ac[s] = 0;
        }
    }

    float acc[8][8];
#pragma unroll
    for (int i = 0; i < 8; ++i)
#pragma unroll
        for (int j = 0; j < 8; ++j) acc[i][j] = 0.f;

    for (int k0 = 0; k0 < K; k0 += 8) {
#pragma unroll
        for (int s = 0; s < 4; ++s) {
            int m = mg[s];
            int kk = k0 + kA;
            float v = 0.f;
            if (m < M) {
                if (AMODE == 0) {
                    v = __ldg(A + (size_t)m * lda + kk);
                } else if (AMODE == 1) {
                    int u = kk / 10, vv = kk - u * 10;
                    v = __ldg(A + (size_t)m * 512 + u) * __ldg(attrs + m * 10 + vv);
                } else if (AMODE == 2) {
                    int u = kk / 10, vv = kk - u * 10;
                    v = __ldg(A + (size_t)an[s] * 512 + 128 + u * 3 + ac[s]) *
                        __ldg(attrs + an[s] * 10 + vv);
                } else {
                    v = __ldg(A + (size_t)an[s] * 512 + 128 + kk * 3 + ac[s]);
                }
            }
            As[kA][mA0 + 32 * s] = v;
        }
#pragma unroll
        for (int s = 0; s < 4; ++s) {
            int kk = kB0 + 2 * s;
            Bs[kk][nB] = __ldg(B + (size_t)(k0 + kk) * Ncols + bn + nB);
        }
        __syncthreads();
#pragma unroll
        for (int k = 0; k < 8; ++k) {
            float4 a0 = *(const float4*)&As[k][row0];
            float4 a1 = *(const float4*)&As[k][row0 + 4];
            float4 b0 = *(const float4*)&Bs[k][col0];
            float4 b1 = *(const float4*)&Bs[k][col0 + 4];
            float a[8] = {a0.x, a0.y, a0.z, a0.w, a1.x, a1.y, a1.z, a1.w};
            float b[8] = {b0.x, b0.y, b0.z, b0.w, b1.x, b1.y, b1.z, b1.w};
#pragma unroll
            for (int i = 0; i < 8; ++i)
#pragma unroll
                for (int j = 0; j < 8; ++j)
                    acc[i][j] = fmaf(a[i], b[j], acc[i][j]);
        }
        __syncthreads();
    }

#pragma unroll
    for (int i = 0; i < 8; ++i) {
        int m = bm + row0 + i;
        if (m >= M) continue;
        float r[8];
#pragma unroll
        for (int j = 0; j < 8; ++j) r[j] = alpha * acc[i][j];
        if (D) {
            size_t doff = (size_t)m * Ncols + bn + col0;
            float4 d0 = __ldg((const float4*)(D + doff));
            float4 d1 = __ldg((const float4*)(D + doff + 4));
            r[0] += d0.x; r[1] += d0.y; r[2] += d0.z; r[3] += d0.w;
            r[4] += d1.x; r[5] += d1.y; r[6] += d1.z; r[7] += d1.w;
        }
        if (OMODE == 0) {
            size_t off = (size_t)m * Ncols + bn + col0;
            *(float4*)(C + off)     = make_float4(r[0], r[1], r[2], r[3]);
            *(float4*)(C + off + 4) = make_float4(r[4], r[5], r[6], r[7]);
        } else if (OMODE == 1) {
            float* base = C + (size_t)m * 512 + bn + col0;
            *(float4*)(base)     = make_float4(r[0], r[1], r[2], r[3]);
            *(float4*)(base + 4) = make_float4(r[4], r[5], r[6], r[7]);
        } else {
            int c = m / NNODE;
            int n = m - c * NNODE;
            float* base = C + (size_t)n * 512 + 128 + (size_t)(bn + col0) * 3 + c;
#pragma unroll
            for (int j = 0; j < 8; ++j) base[j * 3] = r[j];
        }
    }
}

// ---------------- merged GEMM launches ------------------------------------------
// mega1: all GEMMs that depend only on fc hidden / inputs.
// Long-K sc jobs first (LPT), then lin1, then 5000 w-GEMM blocks fill the tail.
__global__ void __launch_bounds__(256) k_mega1(
    const float* __restrict__ nf, const float* __restrict__ attrs,
    const float* __restrict__ l1s, const float* __restrict__ l1v,
    const float* __restrict__ scw_s, const float* __restrict__ scw_v,
    const float* __restrict__ fcw2)
{
    __shared__ __align__(16) float As[8][128];
    __shared__ __align__(16) float Bs[8][128];
    int b = blockIdx.x;
    if (b < 79) {
        sgemm_body<1, 0>(As, Bs, 0, b, nf, scw_s, g_scs, nullptr, attrs,
                         NNODE, 1280, 128, 0, SCN_C);
    } else if (b < 314) {
        sgemm_body<2, 0>(As, Bs, 0, b - 79, nf, scw_v, g_scvt, nullptr, attrs,
                         3 * NNODE, 1280, 128, 0, SCN_C);
    } else if (b < 393) {
        sgemm_body<0, 0>(As, Bs, 0, b - 314, nf, l1s, g_ys, nullptr, nullptr,
                         NNODE, 128, 128, 512, L1S_C);
    } else if (b < 628) {
        sgemm_body<3, 0>(As, Bs, 0, b - 393, nf, l1v, g_yvt, nullptr, nullptr,
                         3 * NNODE, 128, 128, 0, L1S_C);
    } else {
        int l = b - 628;
        sgemm_body<0, 0>(As, Bs, l & 3, l >> 2, g_h, fcw2, g_w, nullptr, nullptr,
                         NEDGE, 64, 512, 64, 0.125f);
    }
}

// mega2: lin2 (s and v) with skip-connection, writing the packed output directly.
__global__ void __launch_bounds__(256) k_mega2(
    const float* __restrict__ l2s, const float* __restrict__ l2v,
    float* __restrict__ out)
{
    __shared__ __align__(16) float As[8][128];
    __shared__ __align__(16) float Bs[8][128];
    int b = blockIdx.x;
    if (b < 79) {
        sgemm_body<0, 1>(As, Bs, 0, b, g_aggs, l2s, out, g_scs, nullptr,
                         NNODE, 256, 128, 256, OUTA_C);
    } else {
        sgemm_body<0, 2>(As, Bs, 0, b - 79, g_aggvt, l2v, out, g_scvt, nullptr,
                         3 * NNODE, 256, 128, 256, OUTA_C);
    }
}

// ---------------- fc layers 0+1 (8->64->64, scaled SiLU, 1 MUFU per silu) ------
__device__ __forceinline__ float siluc(float x)
{
    float xc = fmaxf(x, -20.0f);
    float e = __expf(-xc);                 // 1 MUFU (EX2)
    float y = 1.0f + e;                    // y in (1, ~4.9e8]
    float r = __uint_as_float(0x7EF311C3u - __float_as_uint(y));  // rcp seed
    r = r * (2.0f - y * r);                // 3 Newton steps -> fp32-accurate
    r = r * (2.0f - y * r);
    r = r * (2.0f - y * r);
    return 1.679f * x * r;
}

// 128 threads, 64 edges/block (grid 2500). Thread owns 4 edges x 8 outputs:
// per k-step: 2x LDS.128 (weights, amortized over 4 edges) + 4 bcast LDS + 32 FMA.
__global__ void __launch_bounds__(128) k_fc01(
    const float* __restrict__ ef, const float* __restrict__ w0,
    const float* __restrict__ w1)
{
    __shared__ __align__(16) float w0s[8 * 64];
    __shared__ __align__(16) float w1s[64 * 64];
    __shared__ float efs[64][9];    // pad 9: conflict-free strided reads
    __shared__ float h0s[64][66];   // pad 66: conflict-free strided reads
    const int tid = threadIdx.x;
    const float rs8 = 0.35355339059327373f;  // 1/sqrt(8)
    for (int i = tid; i < 8 * 64; i += 128) w0s[i] = w0[i] * rs8;
    for (int i = tid; i < 1024; i += 128) {
        float4 v = __ldg((const float4*)w1 + i);
        v.x *= 0.125f; v.y *= 0.125f; v.z *= 0.125f; v.w *= 0.125f;
        *(float4*)&w1s[i * 4] = v;
    }
    const int e0 = blockIdx.x * 64;
    {   // stage edge feats: 64 edges x 8 = 128 float4
        float4 v = __ldg((const float4*)(ef + (size_t)e0 * 8) + tid);
        int e = tid >> 1, k4 = (tid & 1) * 4;
        efs[e][k4 + 0] = v.x; efs[e][k4 + 1] = v.y;
        efs[e][k4 + 2] = v.z; efs[e][k4 + 3] = v.w;
    }
    __syncthreads();

    const int warp = tid >> 5, lane = tid & 31;
    const int j8 = (lane & 7) * 8;          // output group
    const int es = warp * 4 + (lane >> 3);  // 0..15: 4-edge set
    const int eb = es * 4;                  // local edge base

    // layer 0: 8 -> 64
    float acc[4][8];
#pragma unroll
    for (int i = 0; i < 4; ++i)
#pragma unroll
        for (int j = 0; j < 8; ++j) acc[i][j] = 0.f;
#pragma unroll
    for (int k = 0; k < 8; ++k) {
        float4 wA = *(const float4*)&w0s[k * 64 + j8];
        float4 wB = *(const float4*)&w0s[k * 64 + j8 + 4];
        float wv[8] = {wA.x, wA.y, wA.z, wA.w, wB.x, wB.y, wB.z, wB.w};
#pragma unroll
        for (int i = 0; i < 4; ++i) {
            float a = efs[eb + i][k];
#pragma unroll
            for (int j = 0; j < 8; ++j) acc[i][j] = fmaf(a, wv[j], acc[i][j]);
        }
    }
#pragma unroll
    for (int i = 0; i < 4; ++i) {
#pragma unroll
        for (int j = 0; j < 8; j += 2) {
            float2 p = make_float2(siluc(acc[i][j]), siluc(acc[i][j + 1]));
            *(float2*)&h0s[eb + i][j8 + j] = p;
        }
    }
    __syncthreads();

    // layer 1: 64 -> 64
#pragma unroll
    for (int i = 0; i < 4; ++i)
#pragma unroll
        for (int j = 0; j < 8; ++j) acc[i][j] = 0.f;
#pragma unroll 8
    for (int k = 0; k < 64; ++k) {
        float4 wA = *(const float4*)&w1s[k * 64 + j8];
        float4 wB = *(const float4*)&w1s[k * 64 + j8 + 4];
        float wv[8] = {wA.x, wA.y, wA.z, wA.w, wB.x, wB.y, wB.z, wB.w};
#pragma unroll
        for (int i = 0; i < 4; ++i) {
            float a = h0s[eb + i][k];
#pragma unroll
            for (int j = 0; j < 8; ++j) acc[i][j] = fmaf(a, wv[j], acc[i][j]);
        }
    }
#pragma unroll
    for (int i = 0; i < 4; ++i) {
        float o[8];
#pragma unroll
        for (int j = 0; j < 8; ++j) o[j] = siluc(acc[i][j]);
        float* dst = g_h + (size_t)(e0 + eb + i) * 64 + j8;
        *(float4*)(dst)     = make_float4(o[0], o[1], o[2], o[3]);
        *(float4*)(dst + 4) = make_float4(o[4], o[5], o[6], o[7]);
    }
}

// ---------------- CSR build ----------------------------------------------------
__global__ void k_count(const int* __restrict__ ei)
{
    int e = blockIdx.x * 256 + threadIdx.x;
    if (e < NEDGE) atomicAdd(&g_cnt[ei[e]], 1);
}

__global__ void k_scan()
{
    __shared__ int sm[256];
    const int tid = threadIdx.x;
    const int CH = (NNODE + 255) / 256;
    int beg = tid * CH;
    int end = min(beg + CH, NNODE);
    int s = 0;
    for (int i = beg; i < end; ++i) s += g_cnt[i];
    sm[tid] = s;
    __syncthreads();
    for (int off = 1; off < 256; off <<= 1) {
        int v = 0;
        if (tid >= off) v = sm[tid - off];
        __syncthreads();
        sm[tid] += v;
        __syncthreads();
    }
    int run = sm[tid] - s;
    for (int i = beg; i < end; ++i) {
        g_rowstart[i] = run;
        g_pos[i] = run;
        run += g_cnt[i];
    }
    if (tid == 255) g_rowstart[NNODE] = sm[255];
}

__global__ void k_fill(const int* __restrict__ ei)
{
    int e = blockIdx.x * 256 + threadIdx.x;
    if (e < NEDGE) {
        int d = ei[e];
        int p = atomicAdd(&g_pos[d], 1);
        g_eid[p] = e;
    }
}

// ---------------- message + aggregation: one warp per node, no float atomics ---
__global__ void __launch_bounds__(256) k_agg(const int* __restrict__ ei,
                                             const float* __restrict__ eattr)
{
    int gw = (blockIdx.x * blockDim.x + threadIdx.x) >> 5;
    int lane = threadIdx.x & 31;
    if (gw >= NNODE) return;
    const int n = gw;
    const int u0 = lane * 4;
    const float inv_sq3 = 0.5773502691896258f;

    float s0[4] = {0, 0, 0, 0}, s1[4] = {0, 0, 0, 0};
    float v2[3][4] = {{0}}, v3[3][4] = {{0}};

    const int beg = g_rowstart[n];
    const int end = g_rowstart[n + 1];
    for (int i = beg; i < end; ++i) {
        int e = g_eid[i];
        float4 ea = __ldg((const float4*)(eattr + (size_t)e * 4));
        int s = ei[NEDGE + e];  // src = edge_index[1]
        const float* wr = g_w + (size_t)e * 512 + u0;
        float4 wss = __ldg((const float4*)(wr));
        float4 wsv = __ldg((const float4*)(wr + 128));
        float4 wvs = __ldg((const float4*)(wr + 256));
        float4 wvv = __ldg((const float4*)(wr + 384));
        const float* yb = g_ys + (size_t)s * 128 + u0;
        float4 xs = __ldg((const float4*)(yb));
        const float* vb = g_yvt + (size_t)s * 128 + u0;
        float4 x0 = __ldg((const float4*)(vb));
        float4 x1 = __ldg((const float4*)(vb + NNODE * 128));
        float4 x2 = __ldg((const float4*)(vb + 2 * NNODE * 128));

        float as_ = ea.x, av0 = ea.y, av1 = ea.z, av2 = ea.w;
        float WSS[4] = {wss.x, wss.y, wss.z, wss.w};
        float WSV[4] = {wsv.x, wsv.y, wsv.z, wsv.w};
        float WVS[4] = {wvs.x, wvs.y, wvs.z, wvs.w};
        float WVV[4] = {wvv.x, wvv.y, wvv.z, wvv.w};
        float XS[4]  = {xs.x, xs.y, xs.z, xs.w};
        float X0[4]  = {x0.x, x0.y, x0.z, x0.w};
        float X1[4]  = {x1.x, x1.y, x1.z, x1.w};
        float X2[4]  = {x2.x, x2.y, x2.z, x2.w};
#pragma unroll
        for (int t = 0; t < 4; ++t) {
            s0[t] = fmaf(WSS[t] * as_, XS[t], s0[t]);
            float dot = X0[t] * av0 + X1[t] * av1 + X2[t] * av2;
            s1[t] = fmaf(WVV[t] * inv_sq3, dot, s1[t]);
            float tsv = WSV[t] * XS[t];
            v2[0][t] = fmaf(tsv, av0, v2[0][t]);
            v2[1][t] = fmaf(tsv, av1, v2[1][t]);
            v2[2][t] = fmaf(tsv, av2, v2[2][t]);
            float tvs = WVS[t] * as_;
            v3[0][t] = fmaf(tvs, X0[t], v3[0][t]);
            v3[1][t] = fmaf(tvs, X1[t], v3[1][t]);
            v3[2][t] = fmaf(tvs, X2[t], v3[2][t]);
        }
    }

    float* sp = g_aggs + (size_t)n * 256 + u0;
    *(float4*)(sp)       = make_float4(s0[0], s0[1], s0[2], s0[3]);
    *(float4*)(sp + 128) = make_float4(s1[0], s1[1], s1[2], s1[3]);
#pragma unroll
    for (int c = 0; c < 3; ++c) {
        float* vp = g_aggvt + (size_t)c * NNODE * 256 + (size_t)n * 256 + u0;
        *(float4*)(vp)       = make_float4(v2[c][0], v2[c][1], v2[c][2], v2[c][3]);
        *(float4*)(vp + 128) = make_float4(v3[c][0], v3[c][1], v3[c][2], v3[c][3]);
    }
}

// ---------------- launch -------------------------------------------------------
extern "C" void kernel_launch(void* const* d_in, const int* in_sizes, int n_in,
                              void* d_out, int out_size)
{
    const float* node_feats = (const float*)d_in[0];
    const float* node_attrs = (const float*)d_in[1];
    const float* edge_feats = (const float*)d_in[2];
    const float* edge_attrs = (const float*)d_in[3];
    const int*   edge_index = (const int*)d_in[4];
    const float* lin1_ws = (const float*)d_in[5];
    const float* lin1_wv = (const float*)d_in[6];
    const float* fc_w0   = (const float*)d_in[7];
    const float* fc_w1   = (const float*)d_in[8];
    const float* fc_w2   = (const float*)d_in[9];
    const float* lin2_ws = (const float*)d_in[10];
    const float* lin2_wv = (const float*)d_in[11];
    const float* sc_ws   = (const float*)d_in[12];
    const float* sc_wv   = (const float*)d_in[13];
    float* out = (float*)d_out;

    int* p_cnt;
    cudaGetSymbolAddress((void**)&p_cnt, g_cnt);

    // CSR build
    cudaMemsetAsync(p_cnt, 0, NNODE * sizeof(int));
    k_count<<<625, 256>>>(edge_index);
    k_scan<<<1, 256>>>();
    k_fill<<<625, 256>>>(edge_index);

    // fc small layers -> g_h
    k_fc01<<<2500, 128>>>(edge_feats, fc_w0, fc_w1);

    // ALL independent GEMMs in one launch:
    // [0,79) sc_s | [79,314) sc_v | [314,393) y_s | [393,628) y_v | [628,5628) w
    k_mega1<<<5628, 256>>>(node_feats, node_attrs, lin1_ws, lin1_wv,
                           sc_ws, sc_wv, fc_w2);

    // messages + segment sum (CSR, warp per node, register accumulators)
    k_agg<<<1250, 256>>>(edge_index, edge_attrs);

    // lin2 (s + v) + skip connection, writing packed output directly
    k_mega2<<<314, 256>>>(lin2_ws, lin2_wv, out);
}